// round 1
// baseline (speedup 1.0000x reference)
#include <cuda_runtime.h>
#include <cstdint>

#define NTOK 8192
#define HDIM 1024
#define FDIM 4096
#define NEXP 8

// ---------------- scratch (device globals: no allocation allowed) ----------
__device__ int   g_cnt[NEXP];
__device__ int   g_off[NEXP];
__device__ int   g_tok[NEXP * NTOK];
__device__ float g_wgt[NEXP * NTOK];
// compact h buffer: exactly N*K = 16384 rows of 4096 fp32 (268 MB)
__device__ float g_hbuf[(size_t)(2 * NTOK) * FDIM];

// ---------------- helpers ---------------------------------------------------
__device__ __forceinline__ float tf32r(float x) {
    uint32_t u;
    asm("cvt.rna.tf32.f32 %0, %1;" : "=r"(u) : "f"(x));
    return __uint_as_float(u);
}

__device__ __forceinline__ void mma_tf32(float* c, const uint32_t* a, const uint32_t* b) {
    asm("mma.sync.aligned.m16n8k8.row.col.f32.tf32.tf32.f32 "
        "{%0,%1,%2,%3}, {%4,%5,%6,%7}, {%8,%9}, {%0,%1,%2,%3};"
        : "+f"(c[0]), "+f"(c[1]), "+f"(c[2]), "+f"(c[3])
        : "r"(a[0]), "r"(a[1]), "r"(a[2]), "r"(a[3]),
          "r"(b[0]), "r"(b[1]));
}

__device__ __forceinline__ float gelu_exact(float v) {
    return 0.5f * v * (1.0f + erff(v * 0.70710678118654752440f));
}

// ---------------- kernel 0: zero out + counters -----------------------------
__global__ void zero_kernel(float4* out, int nf4) {
    int i = blockIdx.x * 256 + threadIdx.x;
    if (i < nf4) out[i] = make_float4(0.f, 0.f, 0.f, 0.f);
    if (i < NEXP) g_cnt[i] = 0;
}

// ---------------- kernel 1: router (one warp per token) ---------------------
__global__ void router_kernel(const float* __restrict__ x,
                              const float* __restrict__ grad,
                              const float* __restrict__ Wr,
                              const float* __restrict__ br) {
    int n = blockIdx.x * 8 + (threadIdx.x >> 5);
    int lane = threadIdx.x & 31;
    if (n >= NTOK) return;

    float acc[NEXP];
    #pragma unroll
    for (int e = 0; e < NEXP; e++) acc[e] = 0.f;

    const float* xr = x + (size_t)n * HDIM;
    for (int h = lane; h < HDIM; h += 32) {
        float xv = xr[h];
        const float* wrow = Wr + h * NEXP;
        #pragma unroll
        for (int e = 0; e < NEXP; e++) acc[e] = fmaf(xv, wrow[e], acc[e]);
    }
    #pragma unroll
    for (int e = 0; e < NEXP; e++) {
        #pragma unroll
        for (int off = 16; off > 0; off >>= 1)
            acc[e] += __shfl_xor_sync(0xffffffffu, acc[e], off);
    }
    if (lane == 0) {
        float gv = grad[n];
        float l[NEXP];
        #pragma unroll
        for (int e = 0; e < NEXP; e++)
            l[e] = acc[e] + gv * Wr[HDIM * NEXP + e] + br[e];
        float m = l[0];
        #pragma unroll
        for (int e = 1; e < NEXP; e++) m = fmaxf(m, l[e]);
        float p[NEXP];
        float s = 0.f;
        #pragma unroll
        for (int e = 0; e < NEXP; e++) { p[e] = expf(l[e] - m); s += p[e]; }
        float inv = 1.f / s;
        // top-1 then top-2, lowest index wins ties (jax top_k semantics)
        int i1 = 0;
        #pragma unroll
        for (int e = 1; e < NEXP; e++) if (p[e] > p[i1]) i1 = e;
        int i2 = (i1 == 0) ? 1 : 0;
        #pragma unroll
        for (int e = 0; e < NEXP; e++) if (e != i1 && p[e] > p[i2]) i2 = e;

        int s1 = atomicAdd(&g_cnt[i1], 1);
        g_tok[i1 * NTOK + s1] = n;  g_wgt[i1 * NTOK + s1] = p[i1] * inv;
        int s2 = atomicAdd(&g_cnt[i2], 1);
        g_tok[i2 * NTOK + s2] = n;  g_wgt[i2 * NTOK + s2] = p[i2] * inv;
    }
}

// ---------------- kernel 2: exclusive prefix (E=8, trivial) -----------------
__global__ void prefix_kernel() {
    if (threadIdx.x == 0) {
        int s = 0;
        #pragma unroll
        for (int e = 0; e < NEXP; e++) { g_off[e] = s; s += g_cnt[e]; }
    }
}

// ---------------- kernel 3: grouped GEMM1 + bias + GELU ---------------------
// C1[r, f] = gelu( x[tok[r], :] @ W1[e][:, f] + b1[e][f] ),  tile 128x128x32
__global__ __launch_bounds__(256) void gemm1_kernel(
    const float* __restrict__ x,
    const float* __restrict__ W1,
    const float* __restrict__ b1)
{
    const int e = blockIdx.z;
    const int cnt = g_cnt[e];
    const int row0 = blockIdx.y * 128;
    if (row0 >= cnt) return;
    const int n0 = blockIdx.x * 128;
    const int off = g_off[e];

    __shared__ __align__(16) float As[128][36];
    __shared__ __align__(16) float Bs[32][136];

    const int tid  = threadIdx.x;
    const int lane = tid & 31;
    const int warp = tid >> 5;
    const int wm = warp >> 2;   // 0..1
    const int wn = warp & 3;    // 0..3
    const int g  = lane >> 2;
    const int tig = lane & 3;

    const float* aptr[4];
    int ar[4];
    #pragma unroll
    for (int i = 0; i < 4; i++) {
        int idx = tid + i * 256;
        int r = idx >> 3;
        int gr = row0 + r;
        int sr = (gr < cnt) ? gr : (cnt - 1);
        int tok = g_tok[e * NTOK + sr];
        aptr[i] = x + (size_t)tok * HDIM + ((idx & 7) << 2);
        ar[i] = r;
    }
    const float* W1e = W1 + (size_t)e * HDIM * FDIM + n0;

    float acc[4][4][4];
    #pragma unroll
    for (int mt = 0; mt < 4; mt++)
        #pragma unroll
        for (int nt = 0; nt < 4; nt++)
            #pragma unroll
            for (int i = 0; i < 4; i++) acc[mt][nt][i] = 0.f;

    for (int k0 = 0; k0 < HDIM; k0 += 32) {
        #pragma unroll
        for (int i = 0; i < 4; i++) {
            int idx = tid + i * 256;
            float4 v = *(const float4*)(aptr[i] + k0);
            v.x = tf32r(v.x); v.y = tf32r(v.y); v.z = tf32r(v.z); v.w = tf32r(v.w);
            *(float4*)&As[ar[i]][(idx & 7) << 2] = v;
        }
        #pragma unroll
        for (int i = 0; i < 4; i++) {
            int idx = tid + i * 256;
            int kr = idx >> 5;
            int c4 = (idx & 31) << 2;
            float4 v = *(const float4*)(W1e + (size_t)(k0 + kr) * FDIM + c4);
            v.x = tf32r(v.x); v.y = tf32r(v.y); v.z = tf32r(v.z); v.w = tf32r(v.w);
            *(float4*)&Bs[kr][c4] = v;
        }
        __syncthreads();
        #pragma unroll
        for (int ks = 0; ks < 4; ks++) {
            int kb = ks * 8;
            uint32_t a[4][4], b[4][2];
            #pragma unroll
            for (int mt = 0; mt < 4; mt++) {
                int m = wm * 64 + mt * 16 + g;
                a[mt][0] = __float_as_uint(As[m    ][kb + tig    ]);
                a[mt][1] = __float_as_uint(As[m + 8][kb + tig    ]);
                a[mt][2] = __float_as_uint(As[m    ][kb + tig + 4]);
                a[mt][3] = __float_as_uint(As[m + 8][kb + tig + 4]);
            }
            #pragma unroll
            for (int nt = 0; nt < 4; nt++) {
                int nn = wn * 32 + nt * 8 + g;
                b[nt][0] = __float_as_uint(Bs[kb + tig    ][nn]);
                b[nt][1] = __float_as_uint(Bs[kb + tig + 4][nn]);
            }
            #pragma unroll
            for (int mt = 0; mt < 4; mt++)
                #pragma unroll
                for (int nt = 0; nt < 4; nt++)
                    mma_tf32(acc[mt][nt], a[mt], b[nt]);
        }
        __syncthreads();
    }

    const float* b1e = b1 + e * FDIM + n0;
    #pragma unroll
    for (int mt = 0; mt < 4; mt++) {
        int rl = wm * 64 + mt * 16 + g;
        #pragma unroll
        for (int half = 0; half < 2; half++) {
            int gr = row0 + rl + half * 8;
            if (gr < cnt) {
                float* hrow = g_hbuf + (size_t)(off + gr) * FDIM + n0;
                #pragma unroll
                for (int nt = 0; nt < 4; nt++) {
                    int c = wn * 32 + nt * 8 + tig * 2;
                    float v0 = gelu_exact(acc[mt][nt][half * 2 + 0] + b1e[c]);
                    float v1 = gelu_exact(acc[mt][nt][half * 2 + 1] + b1e[c + 1]);
                    hrow[c]     = v0;
                    hrow[c + 1] = v1;
                }
            }
        }
    }
}

// ---------------- kernel 4: grouped GEMM2 + bias + weighted scatter-add -----
// out[tok[r], :] += w[r] * ( h[r, :] @ W2[e] + b2[e] )
__global__ __launch_bounds__(256) void gemm2_kernel(
    const float* __restrict__ W2,
    const float* __restrict__ b2,
    float* __restrict__ out)
{
    const int e = blockIdx.z;
    const int cnt = g_cnt[e];
    const int row0 = blockIdx.y * 128;
    if (row0 >= cnt) return;
    const int n0 = blockIdx.x * 128;
    const int off = g_off[e];

    __shared__ __align__(16) float As[128][36];
    __shared__ __align__(16) float Bs[32][136];

    const int tid  = threadIdx.x;
    const int lane = tid & 31;
    const int warp = tid >> 5;
    const int wm = warp >> 2;
    const int wn = warp & 3;
    const int g  = lane >> 2;
    const int tig = lane & 3;

    const float* aptr[4];
    int ar[4];
    #pragma unroll
    for (int i = 0; i < 4; i++) {
        int idx = tid + i * 256;
        int r = idx >> 3;
        int gr = row0 + r;
        int sr = (gr < cnt) ? gr : (cnt - 1);
        aptr[i] = g_hbuf + (size_t)(off + sr) * FDIM + ((idx & 7) << 2);
        ar[i] = r;
    }
    const float* W2e = W2 + (size_t)e * FDIM * HDIM + n0;

    float acc[4][4][4];
    #pragma unroll
    for (int mt = 0; mt < 4; mt++)
        #pragma unroll
        for (int nt = 0; nt < 4; nt++)
            #pragma unroll
            for (int i = 0; i < 4; i++) acc[mt][nt][i] = 0.f;

    for (int k0 = 0; k0 < FDIM; k0 += 32) {
        #pragma unroll
        for (int i = 0; i < 4; i++) {
            int idx = tid + i * 256;
            float4 v = *(const float4*)(aptr[i] + k0);
            v.x = tf32r(v.x); v.y = tf32r(v.y); v.z = tf32r(v.z); v.w = tf32r(v.w);
            *(float4*)&As[ar[i]][(idx & 7) << 2] = v;
        }
        #pragma unroll
        for (int i = 0; i < 4; i++) {
            int idx = tid + i * 256;
            int kr = idx >> 5;
            int c4 = (idx & 31) << 2;
            float4 v = *(const float4*)(W2e + (size_t)(k0 + kr) * HDIM + c4);
            v.x = tf32r(v.x); v.y = tf32r(v.y); v.z = tf32r(v.z); v.w = tf32r(v.w);
            *(float4*)&Bs[kr][c4] = v;
        }
        __syncthreads();
        #pragma unroll
        for (int ks = 0; ks < 4; ks++) {
            int kb = ks * 8;
            uint32_t a[4][4], b[4][2];
            #pragma unroll
            for (int mt = 0; mt < 4; mt++) {
                int m = wm * 64 + mt * 16 + g;
                a[mt][0] = __float_as_uint(As[m    ][kb + tig    ]);
                a[mt][1] = __float_as_uint(As[m + 8][kb + tig    ]);
                a[mt][2] = __float_as_uint(As[m    ][kb + tig + 4]);
                a[mt][3] = __float_as_uint(As[m + 8][kb + tig + 4]);
            }
            #pragma unroll
            for (int nt = 0; nt < 4; nt++) {
                int nn = wn * 32 + nt * 8 + g;
                b[nt][0] = __float_as_uint(Bs[kb + tig    ][nn]);
                b[nt][1] = __float_as_uint(Bs[kb + tig + 4][nn]);
            }
            #pragma unroll
            for (int mt = 0; mt < 4; mt++)
                #pragma unroll
                for (int nt = 0; nt < 4; nt++)
                    mma_tf32(acc[mt][nt], a[mt], b[nt]);
        }
        __syncthreads();
    }

    const float* b2e = b2 + e * HDIM + n0;
    #pragma unroll
    for (int mt = 0; mt < 4; mt++) {
        int rl = wm * 64 + mt * 16 + g;
        #pragma unroll
        for (int half = 0; half < 2; half++) {
            int gr = row0 + rl + half * 8;
            if (gr < cnt) {
                int   tok = g_tok[e * NTOK + gr];
                float w   = g_wgt[e * NTOK + gr];
                float* orow = out + (size_t)tok * HDIM + n0;
                #pragma unroll
                for (int nt = 0; nt < 4; nt++) {
                    int c = wn * 32 + nt * 8 + tig * 2;
                    float v0 = w * (acc[mt][nt][half * 2 + 0] + b2e[c]);
                    float v1 = w * (acc[mt][nt][half * 2 + 1] + b2e[c + 1]);
                    atomicAdd(&orow[c],     v0);
                    atomicAdd(&orow[c + 1], v1);
                }
            }
        }
    }
}

// ---------------- launch -----------------------------------------------------
extern "C" void kernel_launch(void* const* d_in, const int* in_sizes, int n_in,
                              void* d_out, int out_size) {
    const float* x    = (const float*)d_in[0];
    const float* grad = (const float*)d_in[1];
    const float* Wr   = (const float*)d_in[2];
    const float* br   = (const float*)d_in[3];
    const float* W1   = (const float*)d_in[4];
    const float* b1   = (const float*)d_in[5];
    const float* W2   = (const float*)d_in[6];
    const float* b2   = (const float*)d_in[7];
    float* out = (float*)d_out;

    int nf4 = out_size / 4;
    zero_kernel<<<(nf4 + 255) / 256, 256>>>((float4*)out, nf4);
    router_kernel<<<NTOK / 8, 256>>>(x, grad, Wr, br);
    prefix_kernel<<<1, 32>>>();
    gemm1_kernel<<<dim3(FDIM / 128, NTOK / 128, NEXP), 256>>>(x, W1, b1);
    gemm2_kernel<<<dim3(HDIM / 128, NTOK / 128, NEXP), 256>>>(W2, b2, out);
}

// round 3
// speedup vs baseline: 1.1258x; 1.1258x over previous
#include <cuda_runtime.h>
#include <cstdint>

#define NTOK 8192
#define HDIM 1024
#define FDIM 4096
#define NEXP 8

#define BM 128
#define BN 256
#define BK 32
#define NSTAGE 3

// SMEM layout (bytes)
#define AS_STRIDE_F 36                 /* floats per A row (pad: 32+4) */
#define BS_STRIDE_F 264                /* floats per B row (pad: 256+8) */
#define A_STAGE (BM * AS_STRIDE_F * 4) /* 18432 */
#define B_STAGE (BK * BS_STRIDE_F * 4) /* 33792 */
#define OFF_TOK  0
#define OFF_WGT  512
#define OFF_BIAS 1024
#define OFF_A    2048
#define OFF_B    (OFF_A + NSTAGE * A_STAGE)
#define SMEM_TOTAL (OFF_B + NSTAGE * B_STAGE)   /* 158720 */

// ---------------- scratch (device globals: no allocation allowed) ----------
__device__ int   g_cnt[NEXP];
__device__ int   g_off[NEXP];
__device__ int   g_tok[NEXP * NTOK];
__device__ float g_wgt[NEXP * NTOK];
__device__ float g_hbuf[(size_t)(2 * NTOK) * FDIM];            // 256 MB (tf32-rounded)
__device__ float g_xr  [(size_t)NTOK * HDIM];                  // 32 MB  (tf32-rounded x)
__device__ float g_w1r [(size_t)NEXP * (size_t)HDIM * FDIM];   // 128 MB (rounded W1, [e][h][f])
__device__ float g_w2r [(size_t)NEXP * (size_t)FDIM * HDIM];   // 128 MB (rounded W2, [e][f][h])

// ---------------- helpers ---------------------------------------------------
__device__ __forceinline__ uint32_t smem_u32(const void* p) {
    uint32_t a;
    asm("{ .reg .u64 t; cvta.to.shared.u64 t, %1; cvt.u32.u64 %0, t; }" : "=r"(a) : "l"(p));
    return a;
}

__device__ __forceinline__ float tf32r(float x) {
    uint32_t u;
    asm("cvt.rna.tf32.f32 %0, %1;" : "=r"(u) : "f"(x));
    return __uint_as_float(u);
}

__device__ __forceinline__ void mma_tf32(float* c, const uint32_t* a, const uint32_t* b) {
    asm("mma.sync.aligned.m16n8k8.row.col.f32.tf32.tf32.f32 "
        "{%0,%1,%2,%3}, {%4,%5,%6,%7}, {%8,%9}, {%0,%1,%2,%3};"
        : "+f"(c[0]), "+f"(c[1]), "+f"(c[2]), "+f"(c[3])
        : "r"(a[0]), "r"(a[1]), "r"(a[2]), "r"(a[3]),
          "r"(b[0]), "r"(b[1]));
}

__device__ __forceinline__ float gelu_exact(float v) {
    return 0.5f * v * (1.0f + erff(v * 0.70710678118654752440f));
}

#define CP16(dst, src) \
    asm volatile("cp.async.cg.shared.global [%0], [%1], 16;" \
                 :: "r"((uint32_t)(dst)), "l"(__cvta_generic_to_global(src)))
#define CP_COMMIT() asm volatile("cp.async.commit_group;" ::: "memory")

// ---------------- kernel: zero out + counters -------------------------------
__global__ void zero_kernel(float4* out, int nf4) {
    int i = blockIdx.x * 256 + threadIdx.x;
    if (i < nf4) out[i] = make_float4(0.f, 0.f, 0.f, 0.f);
    if (i < NEXP) g_cnt[i] = 0;
}

// ---------------- kernel: tf32-round a big buffer ----------------------------
__global__ void round_kernel(const float4* __restrict__ src, float4* __restrict__ dst) {
    size_t i = (size_t)blockIdx.x * 256 + threadIdx.x;
    float4 v = src[i];
    v.x = tf32r(v.x); v.y = tf32r(v.y); v.z = tf32r(v.z); v.w = tf32r(v.w);
    dst[i] = v;
}

// ---------------- kernel: router (one warp per token) -----------------------
__global__ void router_kernel(const float* __restrict__ x,
                              const float* __restrict__ grad,
                              const float* __restrict__ Wr,
                              const float* __restrict__ br) {
    int n = blockIdx.x * 8 + (threadIdx.x >> 5);
    int lane = threadIdx.x & 31;
    if (n >= NTOK) return;

    float acc[NEXP];
    #pragma unroll
    for (int e = 0; e < NEXP; e++) acc[e] = 0.f;

    const float* xr = x + (size_t)n * HDIM;
    for (int h = lane; h < HDIM; h += 32) {
        float xv = xr[h];
        const float* wrow = Wr + h * NEXP;
        #pragma unroll
        for (int e = 0; e < NEXP; e++) acc[e] = fmaf(xv, wrow[e], acc[e]);
    }
    #pragma unroll
    for (int e = 0; e < NEXP; e++) {
        #pragma unroll
        for (int off = 16; off > 0; off >>= 1)
            acc[e] += __shfl_xor_sync(0xffffffffu, acc[e], off);
    }
    if (lane == 0) {
        float gv = grad[n];
        float l[NEXP];
        #pragma unroll
        for (int e = 0; e < NEXP; e++)
            l[e] = acc[e] + gv * Wr[HDIM * NEXP + e] + br[e];
        float m = l[0];
        #pragma unroll
        for (int e = 1; e < NEXP; e++) m = fmaxf(m, l[e]);
        float p[NEXP];
        float s = 0.f;
        #pragma unroll
        for (int e = 0; e < NEXP; e++) { p[e] = expf(l[e] - m); s += p[e]; }
        float inv = 1.f / s;
        int i1 = 0;
        #pragma unroll
        for (int e = 1; e < NEXP; e++) if (p[e] > p[i1]) i1 = e;
        int i2 = (i1 == 0) ? 1 : 0;
        #pragma unroll
        for (int e = 0; e < NEXP; e++) if (e != i1 && p[e] > p[i2]) i2 = e;

        int s1 = atomicAdd(&g_cnt[i1], 1);
        g_tok[i1 * NTOK + s1] = n;  g_wgt[i1 * NTOK + s1] = p[i1] * inv;
        int s2 = atomicAdd(&g_cnt[i2], 1);
        g_tok[i2 * NTOK + s2] = n;  g_wgt[i2 * NTOK + s2] = p[i2] * inv;
    }
}

__global__ void prefix_kernel() {
    if (threadIdx.x == 0) {
        int s = 0;
        #pragma unroll
        for (int e = 0; e < NEXP; e++) { g_off[e] = s; s += g_cnt[e]; }
    }
}

// ---------------- pipelined grouped GEMM (legacy HMMA tf32) ------------------
// C[BM,BN] = A[BM,KDIM] @ B[KDIM,BN], B row stride NSTRIDE (n contiguous).
// IS_G1: A = g_xr gathered by token, B = g_w1r -> gelu -> g_hbuf
// else : A = g_hbuf rows,            B = g_w2r -> w*(.+b2) atomic -> out
template<int KDIM, int NSTRIDE, bool IS_G1>
__global__ __launch_bounds__(256, 1) void moe_gemm(const float* __restrict__ bias,
                                                   float* __restrict__ out) {
    const int e = blockIdx.z;
    const int cnt = g_cnt[e];
    const int row0 = blockIdx.y * BM;
    if (row0 >= cnt) return;
    const int off = g_off[e];
    const int n0 = blockIdx.x * BN;

    extern __shared__ char smem[];
    const uint32_t sb = smem_u32(smem);
    const int tid  = threadIdx.x;
    const int lane = tid & 31;
    const int warp = tid >> 5;
    const int wm = warp >> 2;       // 0..1
    const int wn = warp & 3;        // 0..3
    const int g  = lane >> 2;       // 0..7
    const int tig = lane & 3;       // 0..3

    int*   tok_s  = (int*)(smem + OFF_TOK);
    float* wgt_s  = (float*)(smem + OFF_WGT);
    float* bias_s = (float*)(smem + OFF_BIAS);

    if (tid < BM) {
        int gr = row0 + tid;
        int sr = (gr < cnt) ? gr : (cnt - 1);
        tok_s[tid] = g_tok[e * NTOK + sr];
        wgt_s[tid] = g_wgt[e * NTOK + sr];
    }
    bias_s[tid] = bias[(size_t)e * (IS_G1 ? FDIM : HDIM) + n0 + tid];
    __syncthreads();

    // ---- load geometry ----
    // A: 4 cp.async/thread: rows (tid>>3)+i*32, 16B chunk (tid&7)
    const float* aptr[4];
    #pragma unroll
    for (int i = 0; i < 4; i++) {
        int r = (tid >> 3) + i * 32;
        if (IS_G1) {
            aptr[i] = g_xr + (size_t)tok_s[r] * HDIM + (tid & 7) * 4;
        } else {
            int gr = row0 + r;
            int sr = (gr < cnt) ? gr : (cnt - 1);
            aptr[i] = g_hbuf + (size_t)(off + sr) * FDIM + (tid & 7) * 4;
        }
    }
    // B: 8 cp.async/thread: k-rows (tid>>6)+i*4, 16B chunk (tid&63)
    const float* wsrc = IS_G1 ? g_w1r : g_w2r;
    const float* bptr0 = wsrc + (size_t)e * HDIM * FDIM
                       + (size_t)(tid >> 6) * NSTRIDE + n0 + (tid & 63) * 4;
    const uint32_t dA0 = sb + OFF_A + (tid >> 3) * (AS_STRIDE_F * 4) + (tid & 7) * 16;
    const uint32_t dB0 = sb + OFF_B + (tid >> 6) * (BS_STRIDE_F * 4) + (tid & 63) * 16;

    constexpr int NK = KDIM / BK;

    #define LOAD_TILE(T) do { \
        const int _s = (T) % NSTAGE; \
        const uint32_t _da = dA0 + _s * A_STAGE; \
        const uint32_t _db = dB0 + _s * B_STAGE; \
        _Pragma("unroll") \
        for (int _i = 0; _i < 4; _i++) \
            CP16(_da + _i * (32 * AS_STRIDE_F * 4), aptr[_i] + (T) * BK); \
        _Pragma("unroll") \
        for (int _i = 0; _i < 8; _i++) \
            CP16(_db + _i * (4 * BS_STRIDE_F * 4), \
                 bptr0 + ((size_t)(T) * BK + _i * 4) * NSTRIDE); \
        CP_COMMIT(); \
    } while (0)

    float acc[4][8][4];
    #pragma unroll
    for (int mt = 0; mt < 4; mt++)
        #pragma unroll
        for (int nt = 0; nt < 8; nt++)
            #pragma unroll
            for (int i = 0; i < 4; i++) acc[mt][nt][i] = 0.f;

    LOAD_TILE(0);
    LOAD_TILE(1);

    for (int kt = 0; kt < NK; ++kt) {
        if (kt + 2 < NK) {
            LOAD_TILE(kt + 2);
            asm volatile("cp.async.wait_group 2;" ::: "memory");
        } else if (kt + 1 < NK) {
            asm volatile("cp.async.wait_group 1;" ::: "memory");
        } else {
            asm volatile("cp.async.wait_group 0;" ::: "memory");
        }
        __syncthreads();

        const int s = kt % NSTAGE;
        const float* As = (const float*)(smem + OFF_A + s * A_STAGE);
        const float* Bs = (const float*)(smem + OFF_B + s * B_STAGE);

        #pragma unroll
        for (int ks = 0; ks < 4; ks++) {
            const int kb = ks * 8;
            uint32_t a[4][4], b[8][2];
            #pragma unroll
            for (int mt = 0; mt < 4; mt++) {
                int m = wm * 64 + mt * 16 + g;
                a[mt][0] = __float_as_uint(As[m * AS_STRIDE_F + kb + tig]);
                a[mt][1] = __float_as_uint(As[(m + 8) * AS_STRIDE_F + kb + tig]);
                a[mt][2] = __float_as_uint(As[m * AS_STRIDE_F + kb + tig + 4]);
                a[mt][3] = __float_as_uint(As[(m + 8) * AS_STRIDE_F + kb + tig + 4]);
            }
            #pragma unroll
            for (int nt = 0; nt < 8; nt++) {
                int nn = wn * 64 + nt * 8 + g;
                b[nt][0] = __float_as_uint(Bs[(kb + tig) * BS_STRIDE_F + nn]);
                b[nt][1] = __float_as_uint(Bs[(kb + tig + 4) * BS_STRIDE_F + nn]);
            }
            #pragma unroll
            for (int mt = 0; mt < 4; mt++)
                #pragma unroll
                for (int nt = 0; nt < 8; nt++)
                    mma_tf32(acc[mt][nt], a[mt], b[nt]);
        }
        __syncthreads();
    }
    #undef LOAD_TILE

    // ---- epilogue ----
    #pragma unroll
    for (int mt = 0; mt < 4; mt++) {
        #pragma unroll
        for (int half = 0; half < 2; half++) {
            const int rl = wm * 64 + mt * 16 + g + half * 8;
            const int gr = row0 + rl;
            if (gr < cnt) {
                if (IS_G1) {
                    float* hrow = g_hbuf + (size_t)(off + gr) * FDIM + n0 + wn * 64;
                    #pragma unroll
                    for (int nt = 0; nt < 8; nt++) {
                        int c = nt * 8 + tig * 2;
                        float b0 = bias_s[wn * 64 + c];
                        float b1v = bias_s[wn * 64 + c + 1];
                        float v0 = tf32r(gelu_exact(acc[mt][nt][half * 2 + 0] + b0));
                        float v1 = tf32r(gelu_exact(acc[mt][nt][half * 2 + 1] + b1v));
                        *(float2*)(hrow + c) = make_float2(v0, v1);
                    }
                } else {
                    const int   tok = tok_s[rl];
                    const float w   = wgt_s[rl];
                    float* orow = out + (size_t)tok * HDIM + n0 + wn * 64;
                    #pragma unroll
                    for (int nt = 0; nt < 8; nt++) {
                        int c = nt * 8 + tig * 2;
                        float v0 = w * (acc[mt][nt][half * 2 + 0] + bias_s[wn * 64 + c]);
                        float v1 = w * (acc[mt][nt][half * 2 + 1] + bias_s[wn * 64 + c + 1]);
                        atomicAdd(orow + c,     v0);
                        atomicAdd(orow + c + 1, v1);
                    }
                }
            }
        }
    }
}

// ---------------- launch -----------------------------------------------------
extern "C" void kernel_launch(void* const* d_in, const int* in_sizes, int n_in,
                              void* d_out, int out_size) {
    const float* x    = (const float*)d_in[0];
    const float* grad = (const float*)d_in[1];
    const float* Wr   = (const float*)d_in[2];
    const float* br   = (const float*)d_in[3];
    const float* W1   = (const float*)d_in[4];
    const float* b1   = (const float*)d_in[5];
    const float* W2   = (const float*)d_in[6];
    const float* b2   = (const float*)d_in[7];
    float* out = (float*)d_out;

    cudaFuncSetAttribute(moe_gemm<HDIM, FDIM, true>,
                         cudaFuncAttributeMaxDynamicSharedMemorySize, SMEM_TOTAL);
    cudaFuncSetAttribute(moe_gemm<FDIM, HDIM, false>,
                         cudaFuncAttributeMaxDynamicSharedMemorySize, SMEM_TOTAL);

    int nf4 = out_size / 4;
    zero_kernel<<<(nf4 + 255) / 256, 256>>>((float4*)out, nf4);

    float* w1r; cudaGetSymbolAddress((void**)&w1r, g_w1r);
    float* w2r; cudaGetSymbolAddress((void**)&w2r, g_w2r);
    float* xr;  cudaGetSymbolAddress((void**)&xr,  g_xr);
    round_kernel<<<NTOK * HDIM / 1024, 256>>>((const float4*)x, (float4*)xr);
    round_kernel<<<NEXP * HDIM * (FDIM / 1024), 256>>>((const float4*)W1, (float4*)w1r);
    round_kernel<<<NEXP * HDIM * (FDIM / 1024), 256>>>((const float4*)W2, (float4*)w2r);

    router_kernel<<<NTOK / 8, 256>>>(x, grad, Wr, br);
    prefix_kernel<<<1, 32>>>();

    moe_gemm<HDIM, FDIM, true>
        <<<dim3(FDIM / BN, NTOK / BM, NEXP), 256, SMEM_TOTAL>>>(b1, nullptr);
    moe_gemm<FDIM, HDIM, false>
        <<<dim3(HDIM / BN, NTOK / BM, NEXP), 256, SMEM_TOTAL>>>(b2, out);
}